// round 15
// baseline (speedup 1.0000x reference)
#include <cuda_runtime.h>
#include <cstdint>

#define NU 100000
#define NI 50000
#define CH 128
#define NE 600000
#define NLAY 2
#define TU ((NU + 127) / 128)
#define TI ((NI + 127) / 128)

// ---------------- scratch (device globals; no allocation allowed) ------------
__device__ float g_xu[NU * CH];     // ping
__device__ float g_xi[NI * CH];
__device__ float g_xu2[NU * CH];    // pong
__device__ float g_xi2[NI * CH];
// weights, bf16 hi/lo split
__device__ unsigned g_W_hi[10 * 8192];
__device__ unsigned g_W_lo[10 * 8192];
// CSR structures
__device__ int g_rp_u[NU + 1];
__device__ int g_rp_i[NI + 1];
__device__ int g_cnt_u[NU];
__device__ int g_cnt_i[NI];
__device__ int g_col_u[NE];
__device__ int g_col_i[NE];

// ---------------- bf16 split helpers -----------------------------------------
__device__ __forceinline__ unsigned packbf(float a, float b) {  // lo=a, hi=b
    unsigned r;
    asm("cvt.rn.satfinite.bf16x2.f32 %0, %1, %2;" : "=r"(r) : "f"(b), "f"(a));
    return r;
}
__device__ __forceinline__ float bflo(unsigned p) { return __uint_as_float(p << 16); }
__device__ __forceinline__ float bfhi(unsigned p) { return __uint_as_float(p & 0xffff0000u); }

__device__ __forceinline__ unsigned smem_u32(const void* p) {
    unsigned a;
    asm("{ .reg .u64 t; cvta.to.shared.u64 t, %1; cvt.u32.u64 %0, t; }"
        : "=r"(a) : "l"(p));
    return a;
}
__device__ __forceinline__ void ldsm_x4(unsigned& r0, unsigned& r1, unsigned& r2,
                                        unsigned& r3, unsigned addr) {
    asm volatile("ldmatrix.sync.aligned.m8n8.x4.shared.b16 {%0,%1,%2,%3}, [%4];"
                 : "=r"(r0), "=r"(r1), "=r"(r2), "=r"(r3) : "r"(addr));
}
__device__ __forceinline__ void ldsm_x2t(unsigned& r0, unsigned& r1, unsigned addr) {
    asm volatile("ldmatrix.sync.aligned.m8n8.x2.trans.shared.b16 {%0,%1}, [%2];"
                 : "=r"(r0), "=r"(r1) : "r"(addr));
}
__device__ __forceinline__ void mma16816(float* d, const unsigned* a, const unsigned* b) {
    asm volatile(
        "mma.sync.aligned.m16n8k16.row.col.f32.bf16.bf16.f32 "
        "{%0,%1,%2,%3}, {%4,%5,%6,%7}, {%8,%9}, {%0,%1,%2,%3};"
        : "+f"(d[0]), "+f"(d[1]), "+f"(d[2]), "+f"(d[3])
        : "r"(a[0]), "r"(a[1]), "r"(a[2]), "r"(a[3]), "r"(b[0]), "r"(b[1]));
}

// swizzled chunk index (16B units) for a 128x128 bf16 tile: row r, 16B-chunk c
__device__ __forceinline__ int swz(int r, int c) { return r * 16 + (c ^ (r & 7)); }

// ---------------- shared GEMM core: acc = A_tile @ W_tile (3-term split) -----
__device__ __forceinline__ void do_gemm(const unsigned base, int aHi, int aLo,
                                        int wHi, int wLo, int wm, int wn, int lane,
                                        float acc[4][4][4]) {
#pragma unroll
    for (int mi = 0; mi < 4; mi++)
#pragma unroll
        for (int ni = 0; ni < 4; ni++)
#pragma unroll
            for (int j = 0; j < 4; j++) acc[mi][ni][j] = 0.0f;
#pragma unroll
    for (int pass = 0; pass < 3; pass++) {
        const unsigned Ab = base + ((pass == 2) ? aLo : aHi);
        const unsigned Bb = base + ((pass == 1) ? wLo : wHi);
#pragma unroll
        for (int ks = 0; ks < 8; ks++) {
            unsigned bfr[4][2];
            const int krow = ks * 16 + (lane & 15);
#pragma unroll
            for (int ni = 0; ni < 4; ni++)
                ldsm_x2t(bfr[ni][0], bfr[ni][1], Bb + swz(krow, wn * 4 + ni) * 16);
            const int arow_off = (lane & 7) + ((lane >> 3) & 1) * 8;
            const int achunk = ks * 2 + (lane >> 4);
#pragma unroll
            for (int mi = 0; mi < 4; mi++) {
                unsigned afr[4];
                const int arow = wm * 64 + mi * 16 + arow_off;
                ldsm_x4(afr[0], afr[1], afr[2], afr[3], Ab + swz(arow, achunk) * 16);
#pragma unroll
                for (int ni = 0; ni < 4; ni++) mma16816(acc[mi][ni], afr, bfr[ni]);
            }
        }
    }
}

// load a 32KB bf16 image (global, linear chunks) into swizzled SMEM
__device__ __forceinline__ void load_w32k(const unsigned* g, char* s, int tid) {
    const uint4* gv = (const uint4*)g;
    uint4* sv = (uint4*)s;
#pragma unroll
    for (int q = 0; q < 8; q++) {
        int c = tid + 256 * q;
        sv[swz(c >> 4, c & 15)] = gv[c];
    }
}

// load fp32 A rows -> bf16 hi/lo swizzled SMEM (zero-fill rows >= M)
__device__ __forceinline__ void load_a(const float* X, int row0, int M,
                                       char* shp, char* slp, int tid) {
    uint4* sh = (uint4*)shp;
    uint4* sl = (uint4*)slp;
#pragma unroll
    for (int q = 0; q < 8; q++) {
        int c = tid + 256 * q;
        int r = c >> 4, ch = c & 15;
        int grow = row0 + r;
        float v[8];
#pragma unroll
        for (int j = 0; j < 8; j++) v[j] = 0.0f;
        if (grow < M) {
            const float4* p = (const float4*)(X + (size_t)grow * CH + ch * 8);
            float4 v0 = p[0], v1 = p[1];
            v[0] = v0.x; v[1] = v0.y; v[2] = v0.z; v[3] = v0.w;
            v[4] = v1.x; v[5] = v1.y; v[6] = v1.z; v[7] = v1.w;
        }
        unsigned hi[4], lo[4];
#pragma unroll
        for (int j = 0; j < 4; j++) {
            hi[j] = packbf(v[2 * j], v[2 * j + 1]);
            lo[j] = packbf(v[2 * j] - bflo(hi[j]), v[2 * j + 1] - bfhi(hi[j]));
        }
        int d = swz(r, ch);
        sh[d] = make_uint4(hi[0], hi[1], hi[2], hi[3]);
        sl[d] = make_uint4(lo[0], lo[1], lo[2], lo[3]);
    }
}

// gather A rows via CSR: a = (1+eps)*XS[row] + sum XG[nbr]; -> bf16 hi/lo SMEM
__device__ __forceinline__ void gather_a(const int* __restrict__ rp,
                                         const int* __restrict__ col,
                                         const float* __restrict__ XG,
                                         const float* __restrict__ XS,
                                         float alpha, int row0, int M,
                                         char* shp, char* slp, int wid, int lane) {
#pragma unroll 1
    for (int k = 0; k < 16; k++) {
        const int r = wid * 16 + k;
        const int grow = row0 + r;
        float ax = 0.f, ay = 0.f, az = 0.f, aw = 0.f;
        if (grow < M) {
            const float4 sv = *(const float4*)(XS + (size_t)grow * CH + lane * 4);
            ax = alpha * sv.x; ay = alpha * sv.y; az = alpha * sv.z; aw = alpha * sv.w;
            const int beg = __ldg(&rp[grow]);
            const int end = __ldg(&rp[grow + 1]);
            int j = beg;
            for (; j + 4 <= end; j += 4) {
                int s0 = __ldg(&col[j]), s1 = __ldg(&col[j + 1]);
                int s2 = __ldg(&col[j + 2]), s3 = __ldg(&col[j + 3]);
                const float4 v0 = *(const float4*)(XG + (size_t)s0 * CH + lane * 4);
                const float4 v1 = *(const float4*)(XG + (size_t)s1 * CH + lane * 4);
                const float4 v2 = *(const float4*)(XG + (size_t)s2 * CH + lane * 4);
                const float4 v3 = *(const float4*)(XG + (size_t)s3 * CH + lane * 4);
                ax += (v0.x + v1.x) + (v2.x + v3.x);
                ay += (v0.y + v1.y) + (v2.y + v3.y);
                az += (v0.z + v1.z) + (v2.z + v3.z);
                aw += (v0.w + v1.w) + (v2.w + v3.w);
            }
            for (; j < end; j++) {
                int s = __ldg(&col[j]);
                const float4 v = *(const float4*)(XG + (size_t)s * CH + lane * 4);
                ax += v.x; ay += v.y; az += v.z; aw += v.w;
            }
        }
        unsigned h0 = packbf(ax, ay), h1 = packbf(az, aw);
        unsigned l0 = packbf(ax - bflo(h0), ay - bfhi(h0));
        unsigned l1 = packbf(az - bflo(h1), aw - bfhi(h1));
        const int boff = swz(r, lane >> 1) * 16 + (lane & 1) * 8;
        *(uint2*)(shp + boff) = make_uint2(h0, h1);
        *(uint2*)(slp + boff) = make_uint2(l0, l1);
    }
}

// ---------------- convW: bf16 hi/lo split of 10 weight matrices --------------
__global__ void convW(const float* __restrict__ W_init, const float* __restrict__ mlp_W,
                      unsigned* __restrict__ Whi, unsigned* __restrict__ Wlo) {
    const int m = blockIdx.x >> 3;
    const int seg = blockIdx.x & 7;
    const float* W = (m < 2) ? (W_init + (size_t)m * CH * CH)
                             : (mlp_W + (size_t)(m - 2) * CH * CH);
    const int t = seg * 1024 + threadIdx.x;
    for (int q = 0; q < 4; q++) {
        int tt = t + q * 256;
        float w0 = W[2 * tt], w1 = W[2 * tt + 1];
        unsigned hi = packbf(w0, w1);
        unsigned lo = packbf(w0 - bflo(hi), w1 - bfhi(hi));
        Whi[m * 8192 + tt] = hi;
        Wlo[m * 8192 + tt] = lo;
    }
}

// ---------------- CSR build ---------------------------------------------------
__global__ void hist2(const int* __restrict__ eui, const int* __restrict__ eiu,
                      int* __restrict__ cnt_i, int* __restrict__ cnt_u) {
    int e = blockIdx.x * blockDim.x + threadIdx.x;
    if (e >= NE) return;
    atomicAdd(&cnt_i[__ldg(&eui[NE + e])], 1);
    atomicAdd(&cnt_u[__ldg(&eiu[NE + e])], 1);
}

__global__ __launch_bounds__(1024) void scan2(int* __restrict__ cnt_i, int* __restrict__ rp_i,
                                              int* __restrict__ cnt_u, int* __restrict__ rp_u) {
    __shared__ int part[1024];
    const int n = blockIdx.x ? NU : NI;
    int* cnt = blockIdx.x ? cnt_u : cnt_i;
    int* rp = blockIdx.x ? rp_u : rp_i;
    const int tid = threadIdx.x;
    const int chunk = (n + 1023) / 1024;
    const int lo = tid * chunk;
    const int hi = (lo + chunk < n) ? lo + chunk : n;
    int s = 0;
    for (int i = lo; i < hi; i++) s += cnt[i];
    part[tid] = s;
    __syncthreads();
    for (int off = 1; off < 1024; off <<= 1) {
        int v = (tid >= off) ? part[tid - off] : 0;
        __syncthreads();
        part[tid] += v;
        __syncthreads();
    }
    int run = tid ? part[tid - 1] : 0;
    for (int i = lo; i < hi; i++) {
        int c = cnt[i];
        rp[i] = run;
        cnt[i] = run;
        run += c;
    }
    if (tid == 1023) rp[n] = run;
}

__global__ void fill2(const int* __restrict__ eui, const int* __restrict__ eiu,
                      int* __restrict__ cur_i, int* __restrict__ cur_u,
                      int* __restrict__ col_i, int* __restrict__ col_u) {
    int e = blockIdx.x * blockDim.x + threadIdx.x;
    if (e >= NE) return;
    int di = __ldg(&eui[NE + e]);
    col_i[atomicAdd(&cur_i[di], 1)] = __ldg(&eui[e]);
    int du = __ldg(&eiu[NE + e]);
    col_u[atomicAdd(&cur_u[du], 1)] = __ldg(&eiu[e]);
}

// ---------------- merged init projection GEMM (user + item in one grid) ------
#define IG_WHI 0
#define IG_WLO 32768
#define IG_AHI 65536
#define IG_ALO 98304
#define IG_BIAS 131072
#define IG_TOT (131072 + 512)

__global__ __launch_bounds__(256) void init_gemm(
    const float* __restrict__ x_user, const float* __restrict__ x_item,
    const unsigned* __restrict__ Whi, const unsigned* __restrict__ Wlo,
    const float* __restrict__ b_init, float* __restrict__ xu, float* __restrict__ xi) {
    extern __shared__ char sm[];
    const int tid = threadIdx.x, wid = tid >> 5, lane = tid & 31;
    const bool user = blockIdx.x < TU;
    const int tile = user ? blockIdx.x : blockIdx.x - TU;
    const int M = user ? NU : NI;
    const int row0 = tile * 128;
    const float* X = user ? x_user : x_item;
    const int slot = user ? 0 : 1;
    const float* bias = b_init + (user ? 0 : CH);
    float* Y = user ? xu : xi;

    load_w32k(Whi + slot * 8192, sm + IG_WHI, tid);
    load_w32k(Wlo + slot * 8192, sm + IG_WLO, tid);
    load_a(X, row0, M, sm + IG_AHI, sm + IG_ALO, tid);
    if (tid < 128) ((float*)(sm + IG_BIAS))[tid] = bias[tid];
    __syncthreads();

    const int wm = wid & 1, wn = wid >> 1;
    const unsigned base = smem_u32(sm);
    float acc[4][4][4];
    do_gemm(base, IG_AHI, IG_ALO, IG_WHI, IG_WLO, wm, wn, lane, acc);

    const float* sbias = (const float*)(sm + IG_BIAS);
#pragma unroll
    for (int mi = 0; mi < 4; mi++) {
        const int r = row0 + wm * 64 + mi * 16 + (lane >> 2);
#pragma unroll
        for (int ni = 0; ni < 4; ni++) {
            const int cb = wn * 32 + ni * 8 + (lane & 3) * 2;
            const float b0 = sbias[cb], b1 = sbias[cb + 1];
            if (r < M)
                *(float2*)(Y + (size_t)r * CH + cb) =
                    make_float2(acc[mi][ni][0] + b0, acc[mi][ni][1] + b1);
            if (r + 8 < M)
                *(float2*)(Y + (size_t)(r + 8) * CH + cb) =
                    make_float2(acc[mi][ni][2] + b0, acc[mi][ni][3] + b1);
        }
    }
}

// ------- fused: CSR gather + GIN MLP (2 linears) + LayerNorm + ReLU ----------
// blocks [0,TU) = user tiles, [TU,TU+TI) = item tiles
// Reads xu_r/xi_r, writes out_u/out_i (MUST be distinct buffers: ping-pong).
#define FM_W0HI 0
#define FM_W0LO 32768
#define FM_W1HI 65536
#define FM_W1LO 98304
#define FM_AHI  131072
#define FM_ALO  163840
#define FM_PAR  196608        // bias0,bias1,lng,lnb : 4 x 512B
#define FM_TOT  (196608 + 2048)

__global__ __launch_bounds__(256) void fused_mlp(
    const int* __restrict__ rp_u, const int* __restrict__ col_u,
    const int* __restrict__ rp_i, const int* __restrict__ col_i,
    const float* __restrict__ xu_r, const float* __restrict__ xi_r,
    const float* __restrict__ eps2,
    const unsigned* __restrict__ Whi, const unsigned* __restrict__ Wlo,
    int slot_u0, int slot_i0,
    const float* __restrict__ Bu0, const float* __restrict__ Bu1,
    const float* __restrict__ Bi0, const float* __restrict__ Bi1,
    const float* __restrict__ lngu, const float* __restrict__ lnbu,
    const float* __restrict__ lngi, const float* __restrict__ lnbi,
    float* __restrict__ out_u, float* __restrict__ out_i) {
    extern __shared__ char sm[];
    const int tid = threadIdx.x, wid = tid >> 5, lane = tid & 31;
    const bool user = blockIdx.x < TU;
    const int tile = user ? blockIdx.x : blockIdx.x - TU;
    const int M = user ? NU : NI;
    const int row0 = tile * 128;
    const int s0 = user ? slot_u0 : slot_i0;
    const float* B0 = user ? Bu0 : Bi0;
    const float* B1 = user ? Bu1 : Bi1;
    const float* lg = user ? lngu : lngi;
    const float* lb = user ? lnbu : lnbi;
    float* Y = user ? out_u : out_i;
    const int* rp = user ? rp_u : rp_i;
    const int* col = user ? col_u : col_i;
    const float* XG = user ? xi_r : xu_r;     // gather source
    const float* XS = user ? xu_r : xi_r;     // self
    const float alpha = 1.0f + __ldg(&eps2[user ? 1 : 0]);

    // gather first (starts the long-latency loads before W copies compete)
    gather_a(rp, col, XG, XS, alpha, row0, M, sm + FM_AHI, sm + FM_ALO, wid, lane);
    load_w32k(Whi + (size_t)s0 * 8192, sm + FM_W0HI, tid);
    load_w32k(Wlo + (size_t)s0 * 8192, sm + FM_W0LO, tid);
    load_w32k(Whi + (size_t)(s0 + 1) * 8192, sm + FM_W1HI, tid);
    load_w32k(Wlo + (size_t)(s0 + 1) * 8192, sm + FM_W1LO, tid);
    if (tid < 128) {
        float* par = (float*)(sm + FM_PAR);
        par[tid] = B0[tid];
        par[128 + tid] = B1[tid];
        par[256 + tid] = lg[tid];
        par[384 + tid] = lb[tid];
    }
    __syncthreads();

    const int wm = wid & 1, wn = wid >> 1;
    const unsigned base = smem_u32(sm);
    const float* par = (const float*)(sm + FM_PAR);
    float acc[4][4][4];

    // ---- GEMM1 + bias0 + relu -> rewrite A tile (bf16 hi/lo) in SMEM ----
    do_gemm(base, FM_AHI, FM_ALO, FM_W0HI, FM_W0LO, wm, wn, lane, acc);
    __syncthreads();
#pragma unroll
    for (int mi = 0; mi < 4; mi++) {
        const int r0 = wm * 64 + mi * 16 + (lane >> 2);
#pragma unroll
        for (int ni = 0; ni < 4; ni++) {
            const int cb = wn * 32 + ni * 8 + (lane & 3) * 2;
            const float b0 = par[cb], b1 = par[cb + 1];
            float v0 = fmaxf(acc[mi][ni][0] + b0, 0.f);
            float v1 = fmaxf(acc[mi][ni][1] + b1, 0.f);
            float v2 = fmaxf(acc[mi][ni][2] + b0, 0.f);
            float v3 = fmaxf(acc[mi][ni][3] + b1, 0.f);
            const int boff0 = swz(r0, cb >> 3) * 16 + ((cb & 7) >> 1) * 4;
            const int boff1 = swz(r0 + 8, cb >> 3) * 16 + ((cb & 7) >> 1) * 4;
            unsigned hi = packbf(v0, v1);
            unsigned lo = packbf(v0 - bflo(hi), v1 - bfhi(hi));
            *(unsigned*)(sm + FM_AHI + boff0) = hi;
            *(unsigned*)(sm + FM_ALO + boff0) = lo;
            hi = packbf(v2, v3);
            lo = packbf(v2 - bflo(hi), v3 - bfhi(hi));
            *(unsigned*)(sm + FM_AHI + boff1) = hi;
            *(unsigned*)(sm + FM_ALO + boff1) = lo;
        }
    }
    __syncthreads();

    // ---- GEMM2 + bias1 + relu -> fp32 tile in SMEM (reuse A region) ----
    do_gemm(base, FM_AHI, FM_ALO, FM_W1HI, FM_W1LO, wm, wn, lane, acc);
    __syncthreads();
    float* ftile = (float*)(sm + FM_AHI);
#pragma unroll
    for (int mi = 0; mi < 4; mi++) {
        const int r0 = wm * 64 + mi * 16 + (lane >> 2);
#pragma unroll
        for (int ni = 0; ni < 4; ni++) {
            const int cb = wn * 32 + ni * 8 + (lane & 3) * 2;
            const float b0 = par[128 + cb], b1 = par[128 + cb + 1];
            *(float2*)&ftile[r0 * 128 + cb] =
                make_float2(fmaxf(acc[mi][ni][0] + b0, 0.f), fmaxf(acc[mi][ni][1] + b1, 0.f));
            *(float2*)&ftile[(r0 + 8) * 128 + cb] =
                make_float2(fmaxf(acc[mi][ni][2] + b0, 0.f), fmaxf(acc[mi][ni][3] + b1, 0.f));
        }
    }
    __syncthreads();

    // ---- LayerNorm + ReLU, warp per row, straight to global ----
    const float4 gv = *(const float4*)&par[256 + lane * 4];
    const float4 bv = *(const float4*)&par[384 + lane * 4];
#pragma unroll
    for (int k = 0; k < 16; k++) {
        const int r = wid * 16 + k;
        const int grow = row0 + r;
        if (grow >= M) break;
        const float4 v = *(const float4*)&ftile[r * 128 + lane * 4];
        float s = v.x + v.y + v.z + v.w;
#pragma unroll
        for (int o = 16; o > 0; o >>= 1) s += __shfl_xor_sync(0xffffffffu, s, o);
        float m = s * (1.0f / CH);
        float dx0 = v.x - m, dx1 = v.y - m, dx2 = v.z - m, dx3 = v.w - m;
        float ss = dx0 * dx0 + dx1 * dx1 + dx2 * dx2 + dx3 * dx3;
#pragma unroll
        for (int o = 16; o > 0; o >>= 1) ss += __shfl_xor_sync(0xffffffffu, ss, o);
        float inv = rsqrtf(ss * (1.0f / CH) + 1e-5f);
        float4 o4;
        o4.x = fmaxf(dx0 * inv * gv.x + bv.x, 0.0f);
        o4.y = fmaxf(dx1 * inv * gv.y + bv.y, 0.0f);
        o4.z = fmaxf(dx2 * inv * gv.z + bv.z, 0.0f);
        o4.w = fmaxf(dx3 * inv * gv.w + bv.w, 0.0f);
        *(float4*)(Y + (size_t)grow * CH + lane * 4) = o4;
    }
}

// ---------------- orchestration ---------------------------------------------
extern "C" void kernel_launch(void* const* d_in, const int* in_sizes, int n_in,
                              void* d_out, int out_size) {
    const float* x_user = (const float*)d_in[0];
    const float* x_item = (const float*)d_in[1];
    const float* W_init = (const float*)d_in[2];
    const float* b_init = (const float*)d_in[3];
    const float* mlp_W  = (const float*)d_in[4];
    const float* mlp_b  = (const float*)d_in[5];
    const float* eps    = (const float*)d_in[6];
    const float* ln_g   = (const float*)d_in[7];
    const float* ln_b   = (const float*)d_in[8];
    const int* edge_ui  = (const int*)d_in[9];
    const int* edge_iu  = (const int*)d_in[10];

    float *xu, *xi, *xu2, *xi2;
    unsigned *Wh, *Wl;
    int *rp_u, *rp_i, *cnt_u, *cnt_i, *col_u, *col_i;
    cudaGetSymbolAddress((void**)&xu, g_xu);
    cudaGetSymbolAddress((void**)&xi, g_xi);
    cudaGetSymbolAddress((void**)&xu2, g_xu2);
    cudaGetSymbolAddress((void**)&xi2, g_xi2);
    cudaGetSymbolAddress((void**)&Wh, g_W_hi);
    cudaGetSymbolAddress((void**)&Wl, g_W_lo);
    cudaGetSymbolAddress((void**)&rp_u, g_rp_u);
    cudaGetSymbolAddress((void**)&rp_i, g_rp_i);
    cudaGetSymbolAddress((void**)&cnt_u, g_cnt_u);
    cudaGetSymbolAddress((void**)&cnt_i, g_cnt_i);
    cudaGetSymbolAddress((void**)&col_u, g_col_u);
    cudaGetSymbolAddress((void**)&col_i, g_col_i);

    cudaFuncSetAttribute(init_gemm, cudaFuncAttributeMaxDynamicSharedMemorySize, IG_TOT);
    cudaFuncSetAttribute(fused_mlp, cudaFuncAttributeMaxDynamicSharedMemorySize, FM_TOT);

    const int eblk = (NE + 255) / 256;

    // ---- CSR build (both directions) ----
    cudaMemsetAsync(cnt_u, 0, NU * sizeof(int), 0);
    cudaMemsetAsync(cnt_i, 0, NI * sizeof(int), 0);
    hist2<<<eblk, 256>>>(edge_ui, edge_iu, cnt_i, cnt_u);
    scan2<<<2, 1024>>>(cnt_i, rp_i, cnt_u, rp_u);
    fill2<<<eblk, 256>>>(edge_ui, edge_iu, cnt_i, cnt_u, col_i, col_u);

    // ---- weights: bf16 hi/lo split once ----
    convW<<<80, 256>>>(W_init, mlp_W, Wh, Wl);

    // ---- init projections (merged user+item) -> ping buffers ----
    init_gemm<<<TU + TI, 256, IG_TOT>>>(x_user, x_item, Wh, Wl, b_init, xu, xi);

    for (int l = 0; l < NLAY; l++) {
        const int si0 = 2 + (l * 2 + 0) * 2;   // item MLP slots (edge type 0)
        const int su0 = 2 + (l * 2 + 1) * 2;   // user MLP slots (edge type 1)
        const float* Bi0 = mlp_b + (size_t)((l * 2 + 0) * 2 + 0) * CH;
        const float* Bi1 = mlp_b + (size_t)((l * 2 + 0) * 2 + 1) * CH;
        const float* Bu0 = mlp_b + (size_t)((l * 2 + 1) * 2 + 0) * CH;
        const float* Bu1 = mlp_b + (size_t)((l * 2 + 1) * 2 + 1) * CH;

        // ping-pong: read buffer (l%2), write buffer ((l+1)%2) or d_out on last
        const float* ru = (l & 1) ? xu2 : xu;
        const float* ri = (l & 1) ? xi2 : xi;
        float* wu = (l == NLAY - 1) ? (float*)d_out : ((l & 1) ? xu : xu2);
        float* wi = (l == NLAY - 1) ? (float*)d_out + (size_t)NU * CH
                                    : ((l & 1) ? xi : xi2);
        fused_mlp<<<TU + TI, 256, FM_TOT>>>(
            rp_u, col_u, rp_i, col_i, ru, ri, eps + l * 2,
            Wh, Wl, su0, si0, Bu0, Bu1, Bi0, Bi1,
            ln_g + (l * 2 + 0) * CH, ln_b + (l * 2 + 0) * CH,
            ln_g + (l * 2 + 1) * CH, ln_b + (l * 2 + 1) * CH,
            wu, wi);
    }
}

// round 16
// speedup vs baseline: 1.3165x; 1.3165x over previous
#include <cuda_runtime.h>
#include <cstdint>

#define NU 100000
#define NI 50000
#define CH 128
#define NE 600000
#define NLAY 2
#define TU ((NU + 127) / 128)
#define TI ((NI + 127) / 128)
#define NSM 152
#define NC_USER 101          // persistent CTAs for user tiles; rest for items

// ---------------- scratch (device globals; no allocation allowed) ------------
__device__ float g_xu[NU * CH];
__device__ float g_xi[NI * CH];
__device__ float g_agg_u[NU * CH];   // combined (1+eps)*x + neighbor sum
__device__ float g_agg_i[NI * CH];
// weights, bf16 hi/lo split
__device__ unsigned g_W_hi[10 * 8192];
__device__ unsigned g_W_lo[10 * 8192];
// CSR structures
__device__ int g_rp_u[NU + 1];
__device__ int g_rp_i[NI + 1];
__device__ int g_cnt_u[NU];
__device__ int g_cnt_i[NI];
__device__ int g_col_u[NE];
__device__ int g_col_i[NE];

// ---------------- bf16 split helpers -----------------------------------------
__device__ __forceinline__ unsigned packbf(float a, float b) {  // lo=a, hi=b
    unsigned r;
    asm("cvt.rn.satfinite.bf16x2.f32 %0, %1, %2;" : "=r"(r) : "f"(b), "f"(a));
    return r;
}
__device__ __forceinline__ float bflo(unsigned p) { return __uint_as_float(p << 16); }
__device__ __forceinline__ float bfhi(unsigned p) { return __uint_as_float(p & 0xffff0000u); }

__device__ __forceinline__ unsigned smem_u32(const void* p) {
    unsigned a;
    asm("{ .reg .u64 t; cvta.to.shared.u64 t, %1; cvt.u32.u64 %0, t; }"
        : "=r"(a) : "l"(p));
    return a;
}
__device__ __forceinline__ void ldsm_x4(unsigned& r0, unsigned& r1, unsigned& r2,
                                        unsigned& r3, unsigned addr) {
    asm volatile("ldmatrix.sync.aligned.m8n8.x4.shared.b16 {%0,%1,%2,%3}, [%4];"
                 : "=r"(r0), "=r"(r1), "=r"(r2), "=r"(r3) : "r"(addr));
}
__device__ __forceinline__ void ldsm_x2t(unsigned& r0, unsigned& r1, unsigned addr) {
    asm volatile("ldmatrix.sync.aligned.m8n8.x2.trans.shared.b16 {%0,%1}, [%2];"
                 : "=r"(r0), "=r"(r1) : "r"(addr));
}
__device__ __forceinline__ void mma16816(float* d, const unsigned* a, const unsigned* b) {
    asm volatile(
        "mma.sync.aligned.m16n8k16.row.col.f32.bf16.bf16.f32 "
        "{%0,%1,%2,%3}, {%4,%5,%6,%7}, {%8,%9}, {%0,%1,%2,%3};"
        : "+f"(d[0]), "+f"(d[1]), "+f"(d[2]), "+f"(d[3])
        : "r"(a[0]), "r"(a[1]), "r"(a[2]), "r"(a[3]), "r"(b[0]), "r"(b[1]));
}

// swizzled chunk index (16B units) for a 128x128 bf16 tile: row r, 16B-chunk c
__device__ __forceinline__ int swz(int r, int c) { return r * 16 + (c ^ (r & 7)); }

// ---------------- shared GEMM core: acc = A_tile @ W_tile (3-term split) -----
__device__ __forceinline__ void do_gemm(const unsigned base, int aHi, int aLo,
                                        int wHi, int wLo, int wm, int wn, int lane,
                                        float acc[4][4][4]) {
#pragma unroll
    for (int mi = 0; mi < 4; mi++)
#pragma unroll
        for (int ni = 0; ni < 4; ni++)
#pragma unroll
            for (int j = 0; j < 4; j++) acc[mi][ni][j] = 0.0f;
#pragma unroll
    for (int pass = 0; pass < 3; pass++) {
        const unsigned Ab = base + ((pass == 2) ? aLo : aHi);
        const unsigned Bb = base + ((pass == 1) ? wLo : wHi);
#pragma unroll
        for (int ks = 0; ks < 8; ks++) {
            unsigned bfr[4][2];
            const int krow = ks * 16 + (lane & 15);
#pragma unroll
            for (int ni = 0; ni < 4; ni++)
                ldsm_x2t(bfr[ni][0], bfr[ni][1], Bb + swz(krow, wn * 4 + ni) * 16);
            const int arow_off = (lane & 7) + ((lane >> 3) & 1) * 8;
            const int achunk = ks * 2 + (lane >> 4);
#pragma unroll
            for (int mi = 0; mi < 4; mi++) {
                unsigned afr[4];
                const int arow = wm * 64 + mi * 16 + arow_off;
                ldsm_x4(afr[0], afr[1], afr[2], afr[3], Ab + swz(arow, achunk) * 16);
#pragma unroll
                for (int ni = 0; ni < 4; ni++) mma16816(acc[mi][ni], afr, bfr[ni]);
            }
        }
    }
}

// load a 32KB bf16 image (global, linear chunks) into swizzled SMEM
__device__ __forceinline__ void load_w32k(const unsigned* g, char* s, int tid) {
    const uint4* gv = (const uint4*)g;
    uint4* sv = (uint4*)s;
#pragma unroll
    for (int q = 0; q < 8; q++) {
        int c = tid + 256 * q;
        sv[swz(c >> 4, c & 15)] = gv[c];
    }
}

// load fp32 A rows -> bf16 hi/lo swizzled SMEM (zero-fill rows >= M)
__device__ __forceinline__ void load_a(const float* X, int row0, int M,
                                       char* shp, char* slp, int tid) {
    uint4* sh = (uint4*)shp;
    uint4* sl = (uint4*)slp;
#pragma unroll
    for (int q = 0; q < 8; q++) {
        int c = tid + 256 * q;
        int r = c >> 4, ch = c & 15;
        int grow = row0 + r;
        float v[8];
#pragma unroll
        for (int j = 0; j < 8; j++) v[j] = 0.0f;
        if (grow < M) {
            const float4* p = (const float4*)(X + (size_t)grow * CH + ch * 8);
            float4 v0 = p[0], v1 = p[1];
            v[0] = v0.x; v[1] = v0.y; v[2] = v0.z; v[3] = v0.w;
            v[4] = v1.x; v[5] = v1.y; v[6] = v1.z; v[7] = v1.w;
        }
        unsigned hi[4], lo[4];
#pragma unroll
        for (int j = 0; j < 4; j++) {
            hi[j] = packbf(v[2 * j], v[2 * j + 1]);
            lo[j] = packbf(v[2 * j] - bflo(hi[j]), v[2 * j + 1] - bfhi(hi[j]));
        }
        int d = swz(r, ch);
        sh[d] = make_uint4(hi[0], hi[1], hi[2], hi[3]);
        sl[d] = make_uint4(lo[0], lo[1], lo[2], lo[3]);
    }
}

// ---------------- convW: bf16 hi/lo split of 10 weight matrices --------------
__global__ void convW(const float* __restrict__ W_init, const float* __restrict__ mlp_W,
                      unsigned* __restrict__ Whi, unsigned* __restrict__ Wlo) {
    const int m = blockIdx.x >> 3;
    const int seg = blockIdx.x & 7;
    const float* W = (m < 2) ? (W_init + (size_t)m * CH * CH)
                             : (mlp_W + (size_t)(m - 2) * CH * CH);
    const int t = seg * 1024 + threadIdx.x;
    for (int q = 0; q < 4; q++) {
        int tt = t + q * 256;
        float w0 = W[2 * tt], w1 = W[2 * tt + 1];
        unsigned hi = packbf(w0, w1);
        unsigned lo = packbf(w0 - bflo(hi), w1 - bfhi(hi));
        Whi[m * 8192 + tt] = hi;
        Wlo[m * 8192 + tt] = lo;
    }
}

// ---------------- CSR build ---------------------------------------------------
__global__ void hist2(const int* __restrict__ eui, const int* __restrict__ eiu,
                      int* __restrict__ cnt_i, int* __restrict__ cnt_u) {
    int e = blockIdx.x * blockDim.x + threadIdx.x;
    if (e >= NE) return;
    atomicAdd(&cnt_i[__ldg(&eui[NE + e])], 1);
    atomicAdd(&cnt_u[__ldg(&eiu[NE + e])], 1);
}

__global__ __launch_bounds__(1024) void scan2(int* __restrict__ cnt_i, int* __restrict__ rp_i,
                                              int* __restrict__ cnt_u, int* __restrict__ rp_u) {
    __shared__ int part[1024];
    const int n = blockIdx.x ? NU : NI;
    int* cnt = blockIdx.x ? cnt_u : cnt_i;
    int* rp = blockIdx.x ? rp_u : rp_i;
    const int tid = threadIdx.x;
    const int chunk = (n + 1023) / 1024;
    const int lo = tid * chunk;
    const int hi = (lo + chunk < n) ? lo + chunk : n;
    int s = 0;
    for (int i = lo; i < hi; i++) s += cnt[i];
    part[tid] = s;
    __syncthreads();
    for (int off = 1; off < 1024; off <<= 1) {
        int v = (tid >= off) ? part[tid - off] : 0;
        __syncthreads();
        part[tid] += v;
        __syncthreads();
    }
    int run = tid ? part[tid - 1] : 0;
    for (int i = lo; i < hi; i++) {
        int c = cnt[i];
        rp[i] = run;
        cnt[i] = run;
        run += c;
    }
    if (tid == 1023) rp[n] = run;
}

__global__ void fill2(const int* __restrict__ eui, const int* __restrict__ eiu,
                      int* __restrict__ cur_i, int* __restrict__ cur_u,
                      int* __restrict__ col_i, int* __restrict__ col_u) {
    int e = blockIdx.x * blockDim.x + threadIdx.x;
    if (e >= NE) return;
    int di = __ldg(&eui[NE + e]);
    col_i[atomicAdd(&cur_i[di], 1)] = __ldg(&eui[e]);
    int du = __ldg(&eiu[NE + e]);
    col_u[atomicAdd(&cur_u[du], 1)] = __ldg(&eiu[e]);
}

// ---------------- merged pull: both directions in one launch ------------------
__global__ void pull_all(const int* __restrict__ rp_i, const int* __restrict__ col_i,
                         const int* __restrict__ rp_u, const int* __restrict__ col_u,
                         const float* __restrict__ xu, const float* __restrict__ xi,
                         const float* __restrict__ eps2,
                         float* __restrict__ ai, float* __restrict__ au) {
    int w = (int)((blockIdx.x * (unsigned)blockDim.x + threadIdx.x) >> 5);
    int lane = threadIdx.x & 31;
    const int* rp;
    const int* col;
    const float* XG;
    const float* XS;
    float* out;
    float alpha;
    int idx;
    if (w < NI) {
        idx = w; rp = rp_i; col = col_i; XG = xu; XS = xi; out = ai;
        alpha = 1.0f + __ldg(&eps2[0]);
    } else {
        idx = w - NI;
        if (idx >= NU) return;
        rp = rp_u; col = col_u; XG = xi; XS = xu; out = au;
        alpha = 1.0f + __ldg(&eps2[1]);
    }
    const float4 sv = *(const float4*)(XS + (size_t)idx * CH + lane * 4);
    float ax = alpha * sv.x, ay = alpha * sv.y, az = alpha * sv.z, aw = alpha * sv.w;
    const int beg = __ldg(&rp[idx]);
    const int end = __ldg(&rp[idx + 1]);
    int j = beg;
    for (; j + 4 <= end; j += 4) {
        int s0 = __ldg(&col[j]), s1 = __ldg(&col[j + 1]);
        int s2 = __ldg(&col[j + 2]), s3 = __ldg(&col[j + 3]);
        const float4 v0 = *(const float4*)(XG + (size_t)s0 * CH + lane * 4);
        const float4 v1 = *(const float4*)(XG + (size_t)s1 * CH + lane * 4);
        const float4 v2 = *(const float4*)(XG + (size_t)s2 * CH + lane * 4);
        const float4 v3 = *(const float4*)(XG + (size_t)s3 * CH + lane * 4);
        ax += (v0.x + v1.x) + (v2.x + v3.x);
        ay += (v0.y + v1.y) + (v2.y + v3.y);
        az += (v0.z + v1.z) + (v2.z + v3.z);
        aw += (v0.w + v1.w) + (v2.w + v3.w);
    }
    for (; j < end; j++) {
        int s = __ldg(&col[j]);
        const float4 v = *(const float4*)(XG + (size_t)s * CH + lane * 4);
        ax += v.x; ay += v.y; az += v.z; aw += v.w;
    }
    *(float4*)(out + (size_t)idx * CH + lane * 4) = make_float4(ax, ay, az, aw);
}

// ---------------- persistent init projection GEMM ----------------------------
// CTAs [0,NC_USER) loop user tiles; [NC_USER,NSM) loop item tiles. W loads once.
#define IG_WHI 0
#define IG_WLO 32768
#define IG_AHI 65536
#define IG_ALO 98304
#define IG_BIAS 131072
#define IG_TOT (131072 + 512)

__global__ __launch_bounds__(256) void init_gemm(
    const float* __restrict__ x_user, const float* __restrict__ x_item,
    const unsigned* __restrict__ Whi, const unsigned* __restrict__ Wlo,
    const float* __restrict__ b_init, float* __restrict__ xu, float* __restrict__ xi) {
    extern __shared__ char sm[];
    const int tid = threadIdx.x, wid = tid >> 5, lane = tid & 31;
    const bool user = blockIdx.x < NC_USER;
    const int cta = user ? blockIdx.x : blockIdx.x - NC_USER;
    const int ncta = user ? NC_USER : (NSM - NC_USER);
    const int ntiles = user ? TU : TI;
    const int M = user ? NU : NI;
    const float* X = user ? x_user : x_item;
    const int slot = user ? 0 : 1;
    const float* bias = b_init + (user ? 0 : CH);
    float* Y = user ? xu : xi;

    load_w32k(Whi + slot * 8192, sm + IG_WHI, tid);
    load_w32k(Wlo + slot * 8192, sm + IG_WLO, tid);
    if (tid < 128) ((float*)(sm + IG_BIAS))[tid] = bias[tid];
    __syncthreads();

    const int wm = wid & 1, wn = wid >> 1;
    const unsigned base = smem_u32(sm);
    const float* sbias = (const float*)(sm + IG_BIAS);

    for (int tile = cta; tile < ntiles; tile += ncta) {
        const int row0 = tile * 128;
        load_a(X, row0, M, sm + IG_AHI, sm + IG_ALO, tid);
        __syncthreads();
        float acc[4][4][4];
        do_gemm(base, IG_AHI, IG_ALO, IG_WHI, IG_WLO, wm, wn, lane, acc);
#pragma unroll
        for (int mi = 0; mi < 4; mi++) {
            const int r = row0 + wm * 64 + mi * 16 + (lane >> 2);
#pragma unroll
            for (int ni = 0; ni < 4; ni++) {
                const int cb = wn * 32 + ni * 8 + (lane & 3) * 2;
                const float b0 = sbias[cb], b1 = sbias[cb + 1];
                if (r < M)
                    *(float2*)(Y + (size_t)r * CH + cb) =
                        make_float2(acc[mi][ni][0] + b0, acc[mi][ni][1] + b1);
                if (r + 8 < M)
                    *(float2*)(Y + (size_t)(r + 8) * CH + cb) =
                        make_float2(acc[mi][ni][2] + b0, acc[mi][ni][3] + b1);
            }
        }
        __syncthreads();   // all warps done reading A before next load_a
    }
}

// -------- persistent fused MLP (2 linears) + LayerNorm + ReLU ----------------
// CTAs [0,NC_USER) loop user tiles; [NC_USER,NSM) loop item tiles.
// W0/W1 hi/lo + bias + LN params load ONCE per CTA; A tile per iteration.
#define FM_W0HI 0
#define FM_W0LO 32768
#define FM_W1HI 65536
#define FM_W1LO 98304
#define FM_AHI  131072
#define FM_ALO  163840
#define FM_PAR  196608        // bias0,bias1,lng,lnb : 4 x 512B
#define FM_TOT  (196608 + 2048)

__global__ __launch_bounds__(256) void fused_mlp(
    const float* __restrict__ agg_u, const float* __restrict__ agg_i,
    const unsigned* __restrict__ Whi, const unsigned* __restrict__ Wlo,
    int slot_u0, int slot_i0,
    const float* __restrict__ Bu0, const float* __restrict__ Bu1,
    const float* __restrict__ Bi0, const float* __restrict__ Bi1,
    const float* __restrict__ lngu, const float* __restrict__ lnbu,
    const float* __restrict__ lngi, const float* __restrict__ lnbi,
    float* __restrict__ out_u, float* __restrict__ out_i) {
    extern __shared__ char sm[];
    const int tid = threadIdx.x, wid = tid >> 5, lane = tid & 31;
    const bool user = blockIdx.x < NC_USER;
    const int cta = user ? blockIdx.x : blockIdx.x - NC_USER;
    const int ncta = user ? NC_USER : (NSM - NC_USER);
    const int ntiles = user ? TU : TI;
    const int M = user ? NU : NI;
    const float* A = user ? agg_u : agg_i;
    const int s0 = user ? slot_u0 : slot_i0;
    const float* B0 = user ? Bu0 : Bi0;
    const float* B1 = user ? Bu1 : Bi1;
    const float* lg = user ? lngu : lngi;
    const float* lb = user ? lnbu : lnbi;
    float* Y = user ? out_u : out_i;

    load_w32k(Whi + (size_t)s0 * 8192, sm + FM_W0HI, tid);
    load_w32k(Wlo + (size_t)s0 * 8192, sm + FM_W0LO, tid);
    load_w32k(Whi + (size_t)(s0 + 1) * 8192, sm + FM_W1HI, tid);
    load_w32k(Wlo + (size_t)(s0 + 1) * 8192, sm + FM_W1LO, tid);
    if (tid < 128) {
        float* par = (float*)(sm + FM_PAR);
        par[tid] = B0[tid];
        par[128 + tid] = B1[tid];
        par[256 + tid] = lg[tid];
        par[384 + tid] = lb[tid];
    }
    __syncthreads();

    const int wm = wid & 1, wn = wid >> 1;
    const unsigned base = smem_u32(sm);
    const float* par = (const float*)(sm + FM_PAR);
    const float4 gv = *(const float4*)&par[256 + lane * 4];
    const float4 bv = *(const float4*)&par[384 + lane * 4];

    for (int tile = cta; tile < ntiles; tile += ncta) {
        const int row0 = tile * 128;
        float acc[4][4][4];

        load_a(A, row0, M, sm + FM_AHI, sm + FM_ALO, tid);
        __syncthreads();

        // ---- GEMM1 + bias0 + relu -> rewrite A tile (bf16 hi/lo) in SMEM ----
        do_gemm(base, FM_AHI, FM_ALO, FM_W0HI, FM_W0LO, wm, wn, lane, acc);
        __syncthreads();
#pragma unroll
        for (int mi = 0; mi < 4; mi++) {
            const int r0 = wm * 64 + mi * 16 + (lane >> 2);
#pragma unroll
            for (int ni = 0; ni < 4; ni++) {
                const int cb = wn * 32 + ni * 8 + (lane & 3) * 2;
                const float b0 = par[cb], b1 = par[cb + 1];
                float v0 = fmaxf(acc[mi][ni][0] + b0, 0.f);
                float v1 = fmaxf(acc[mi][ni][1] + b1, 0.f);
                float v2 = fmaxf(acc[mi][ni][2] + b0, 0.f);
                float v3 = fmaxf(acc[mi][ni][3] + b1, 0.f);
                const int boff0 = swz(r0, cb >> 3) * 16 + ((cb & 7) >> 1) * 4;
                const int boff1 = swz(r0 + 8, cb >> 3) * 16 + ((cb & 7) >> 1) * 4;
                unsigned hi = packbf(v0, v1);
                unsigned lo = packbf(v0 - bflo(hi), v1 - bfhi(hi));
                *(unsigned*)(sm + FM_AHI + boff0) = hi;
                *(unsigned*)(sm + FM_ALO + boff0) = lo;
                hi = packbf(v2, v3);
                lo = packbf(v2 - bflo(hi), v3 - bfhi(hi));
                *(unsigned*)(sm + FM_AHI + boff1) = hi;
                *(unsigned*)(sm + FM_ALO + boff1) = lo;
            }
        }
        __syncthreads();

        // ---- GEMM2 + bias1 + relu -> fp32 tile in SMEM (reuse A region) ----
        do_gemm(base, FM_AHI, FM_ALO, FM_W1HI, FM_W1LO, wm, wn, lane, acc);
        __syncthreads();
        float* ftile = (float*)(sm + FM_AHI);
#pragma unroll
        for (int mi = 0; mi < 4; mi++) {
            const int r0 = wm * 64 + mi * 16 + (lane >> 2);
#pragma unroll
            for (int ni = 0; ni < 4; ni++) {
                const int cb = wn * 32 + ni * 8 + (lane & 3) * 2;
                const float b0 = par[128 + cb], b1 = par[128 + cb + 1];
                *(float2*)&ftile[r0 * 128 + cb] =
                    make_float2(fmaxf(acc[mi][ni][0] + b0, 0.f),
                                fmaxf(acc[mi][ni][1] + b1, 0.f));
                *(float2*)&ftile[(r0 + 8) * 128 + cb] =
                    make_float2(fmaxf(acc[mi][ni][2] + b0, 0.f),
                                fmaxf(acc[mi][ni][3] + b1, 0.f));
            }
        }
        __syncthreads();

        // ---- LayerNorm + ReLU, warp per row, straight to global ----
#pragma unroll
        for (int k = 0; k < 16; k++) {
            const int r = wid * 16 + k;
            const int grow = row0 + r;
            if (grow >= M) break;
            const float4 v = *(const float4*)&ftile[r * 128 + lane * 4];
            float s = v.x + v.y + v.z + v.w;
#pragma unroll
            for (int o = 16; o > 0; o >>= 1) s += __shfl_xor_sync(0xffffffffu, s, o);
            float m = s * (1.0f / CH);
            float dx0 = v.x - m, dx1 = v.y - m, dx2 = v.z - m, dx3 = v.w - m;
            float ss = dx0 * dx0 + dx1 * dx1 + dx2 * dx2 + dx3 * dx3;
#pragma unroll
            for (int o = 16; o > 0; o >>= 1) ss += __shfl_xor_sync(0xffffffffu, ss, o);
            float inv = rsqrtf(ss * (1.0f / CH) + 1e-5f);
            float4 o4;
            o4.x = fmaxf(dx0 * inv * gv.x + bv.x, 0.0f);
            o4.y = fmaxf(dx1 * inv * gv.y + bv.y, 0.0f);
            o4.z = fmaxf(dx2 * inv * gv.z + bv.z, 0.0f);
            o4.w = fmaxf(dx3 * inv * gv.w + bv.w, 0.0f);
            *(float4*)(Y + (size_t)grow * CH + lane * 4) = o4;
        }
        __syncthreads();   // ftile (=A region) fully read before next load_a
    }
}

// ---------------- orchestration ---------------------------------------------
extern "C" void kernel_launch(void* const* d_in, const int* in_sizes, int n_in,
                              void* d_out, int out_size) {
    const float* x_user = (const float*)d_in[0];
    const float* x_item = (const float*)d_in[1];
    const float* W_init = (const float*)d_in[2];
    const float* b_init = (const float*)d_in[3];
    const float* mlp_W  = (const float*)d_in[4];
    const float* mlp_b  = (const float*)d_in[5];
    const float* eps    = (const float*)d_in[6];
    const float* ln_g   = (const float*)d_in[7];
    const float* ln_b   = (const float*)d_in[8];
    const int* edge_ui  = (const int*)d_in[9];
    const int* edge_iu  = (const int*)d_in[10];

    float *xu, *xi, *au, *ai;
    unsigned *Wh, *Wl;
    int *rp_u, *rp_i, *cnt_u, *cnt_i, *col_u, *col_i;
    cudaGetSymbolAddress((void**)&xu, g_xu);
    cudaGetSymbolAddress((void**)&xi, g_xi);
    cudaGetSymbolAddress((void**)&au, g_agg_u);
    cudaGetSymbolAddress((void**)&ai, g_agg_i);
    cudaGetSymbolAddress((void**)&Wh, g_W_hi);
    cudaGetSymbolAddress((void**)&Wl, g_W_lo);
    cudaGetSymbolAddress((void**)&rp_u, g_rp_u);
    cudaGetSymbolAddress((void**)&rp_i, g_rp_i);
    cudaGetSymbolAddress((void**)&cnt_u, g_cnt_u);
    cudaGetSymbolAddress((void**)&cnt_i, g_cnt_i);
    cudaGetSymbolAddress((void**)&col_u, g_col_u);
    cudaGetSymbolAddress((void**)&col_i, g_col_i);

    cudaFuncSetAttribute(init_gemm, cudaFuncAttributeMaxDynamicSharedMemorySize, IG_TOT);
    cudaFuncSetAttribute(fused_mlp, cudaFuncAttributeMaxDynamicSharedMemorySize, FM_TOT);

    const int eblk = (NE + 255) / 256;
    const int pall = ((NI + NU) * 32 + 255) / 256;

    // ---- CSR build (both directions) ----
    cudaMemsetAsync(cnt_u, 0, NU * sizeof(int), 0);
    cudaMemsetAsync(cnt_i, 0, NI * sizeof(int), 0);
    hist2<<<eblk, 256>>>(edge_ui, edge_iu, cnt_i, cnt_u);
    scan2<<<2, 1024>>>(cnt_i, rp_i, cnt_u, rp_u);
    fill2<<<eblk, 256>>>(edge_ui, edge_iu, cnt_i, cnt_u, col_i, col_u);

    // ---- weights: bf16 hi/lo split once ----
    convW<<<80, 256>>>(W_init, mlp_W, Wh, Wl);

    // ---- init projections (persistent, merged user+item) ----
    init_gemm<<<NSM, 256, IG_TOT>>>(x_user, x_item, Wh, Wl, b_init, xu, xi);

    for (int l = 0; l < NLAY; l++) {
        pull_all<<<pall, 256>>>(rp_i, col_i, rp_u, col_u, xu, xi, eps + l * 2, ai, au);

        const int si0 = 2 + (l * 2 + 0) * 2;   // item MLP slots (edge type 0)
        const int su0 = 2 + (l * 2 + 1) * 2;   // user MLP slots (edge type 1)
        const float* Bi0 = mlp_b + (size_t)((l * 2 + 0) * 2 + 0) * CH;
        const float* Bi1 = mlp_b + (size_t)((l * 2 + 0) * 2 + 1) * CH;
        const float* Bu0 = mlp_b + (size_t)((l * 2 + 1) * 2 + 0) * CH;
        const float* Bu1 = mlp_b + (size_t)((l * 2 + 1) * 2 + 1) * CH;

        float* ou = (l == NLAY - 1) ? (float*)d_out : xu;
        float* oi = (l == NLAY - 1) ? (float*)d_out + (size_t)NU * CH : xi;
        fused_mlp<<<NSM, 256, FM_TOT>>>(
            au, ai, Wh, Wl, su0, si0, Bu0, Bu1, Bi0, Bi1,
            ln_g + (l * 2 + 0) * CH, ln_b + (l * 2 + 0) * CH,
            ln_g + (l * 2 + 1) * CH, ln_b + (l * 2 + 1) * CH,
            ou, oi);
    }
}

// round 17
// speedup vs baseline: 1.3221x; 1.0043x over previous
#include <cuda_runtime.h>
#include <cstdint>

#define NU 100000
#define NI 50000
#define CH 128
#define NE 600000
#define NLAY 2
#define TU ((NU + 127) / 128)
#define TI ((NI + 127) / 128)

// ---------------- scratch (device globals; no allocation allowed) ------------
__device__ float g_xu[NU * CH];
__device__ float g_xi[NI * CH];
// aggregated activations as pre-swizzled bf16 hi/lo tile images
__device__ unsigned g_agh_u[TU * 8192];
__device__ unsigned g_agl_u[TU * 8192];
__device__ unsigned g_agh_i[TI * 8192];
__device__ unsigned g_agl_i[TI * 8192];
// weights, bf16 hi/lo split
__device__ unsigned g_W_hi[10 * 8192];
__device__ unsigned g_W_lo[10 * 8192];
// CSR structures
__device__ int g_rp_u[NU + 1];
__device__ int g_rp_i[NI + 1];
__device__ int g_cnt_u[NU];
__device__ int g_cnt_i[NI];
__device__ int g_col_u[NE];
__device__ int g_col_i[NE];

// ---------------- bf16 split helpers -----------------------------------------
__device__ __forceinline__ unsigned packbf(float a, float b) {  // lo=a, hi=b
    unsigned r;
    asm("cvt.rn.satfinite.bf16x2.f32 %0, %1, %2;" : "=r"(r) : "f"(b), "f"(a));
    return r;
}
__device__ __forceinline__ float bflo(unsigned p) { return __uint_as_float(p << 16); }
__device__ __forceinline__ float bfhi(unsigned p) { return __uint_as_float(p & 0xffff0000u); }

__device__ __forceinline__ unsigned smem_u32(const void* p) {
    unsigned a;
    asm("{ .reg .u64 t; cvta.to.shared.u64 t, %1; cvt.u32.u64 %0, t; }"
        : "=r"(a) : "l"(p));
    return a;
}
__device__ __forceinline__ void ldsm_x4(unsigned& r0, unsigned& r1, unsigned& r2,
                                        unsigned& r3, unsigned addr) {
    asm volatile("ldmatrix.sync.aligned.m8n8.x4.shared.b16 {%0,%1,%2,%3}, [%4];"
                 : "=r"(r0), "=r"(r1), "=r"(r2), "=r"(r3) : "r"(addr));
}
__device__ __forceinline__ void ldsm_x2t(unsigned& r0, unsigned& r1, unsigned addr) {
    asm volatile("ldmatrix.sync.aligned.m8n8.x2.trans.shared.b16 {%0,%1}, [%2];"
                 : "=r"(r0), "=r"(r1) : "r"(addr));
}
__device__ __forceinline__ void mma16816(float* d, const unsigned* a, const unsigned* b) {
    asm volatile(
        "mma.sync.aligned.m16n8k16.row.col.f32.bf16.bf16.f32 "
        "{%0,%1,%2,%3}, {%4,%5,%6,%7}, {%8,%9}, {%0,%1,%2,%3};"
        : "+f"(d[0]), "+f"(d[1]), "+f"(d[2]), "+f"(d[3])
        : "r"(a[0]), "r"(a[1]), "r"(a[2]), "r"(a[3]), "r"(b[0]), "r"(b[1]));
}

// swizzled chunk index (16B units) for a 128x128 bf16 tile: row r, 16B-chunk c
__device__ __forceinline__ int swz(int r, int c) { return r * 16 + (c ^ (r & 7)); }

// ---------------- shared GEMM core: acc = A_tile @ W_tile (3-term split) -----
__device__ __forceinline__ void do_gemm(const unsigned base, int aHi, int aLo,
                                        int wHi, int wLo, int wm, int wn, int lane,
                                        float acc[4][4][4]) {
#pragma unroll
    for (int mi = 0; mi < 4; mi++)
#pragma unroll
        for (int ni = 0; ni < 4; ni++)
#pragma unroll
            for (int j = 0; j < 4; j++) acc[mi][ni][j] = 0.0f;
#pragma unroll
    for (int pass = 0; pass < 3; pass++) {
        const unsigned Ab = base + ((pass == 2) ? aLo : aHi);
        const unsigned Bb = base + ((pass == 1) ? wLo : wHi);
#pragma unroll
        for (int ks = 0; ks < 8; ks++) {
            unsigned bfr[4][2];
            const int krow = ks * 16 + (lane & 15);
#pragma unroll
            for (int ni = 0; ni < 4; ni++)
                ldsm_x2t(bfr[ni][0], bfr[ni][1], Bb + swz(krow, wn * 4 + ni) * 16);
            const int arow_off = (lane & 7) + ((lane >> 3) & 1) * 8;
            const int achunk = ks * 2 + (lane >> 4);
#pragma unroll
            for (int mi = 0; mi < 4; mi++) {
                unsigned afr[4];
                const int arow = wm * 64 + mi * 16 + arow_off;
                ldsm_x4(afr[0], afr[1], afr[2], afr[3], Ab + swz(arow, achunk) * 16);
#pragma unroll
                for (int ni = 0; ni < 4; ni++) mma16816(acc[mi][ni], afr, bfr[ni]);
            }
        }
    }
}

// load a 32KB bf16 image (global, linear chunks) into swizzled SMEM
__device__ __forceinline__ void load_w32k(const unsigned* g, char* s, int tid) {
    const uint4* gv = (const uint4*)g;
    uint4* sv = (uint4*)s;
#pragma unroll
    for (int q = 0; q < 8; q++) {
        int c = tid + 256 * q;
        sv[swz(c >> 4, c & 15)] = gv[c];
    }
}

// copy pre-swizzled 32KB images (hi+lo) global -> SMEM
__device__ __forceinline__ void copy_a(const unsigned* gh, const unsigned* gl,
                                       char* shp, char* slp, int tid) {
    const uint4* h = (const uint4*)gh;
    const uint4* l = (const uint4*)gl;
    uint4* sh = (uint4*)shp;
    uint4* sl = (uint4*)slp;
#pragma unroll
    for (int q = 0; q < 8; q++) {
        int c = tid + 256 * q;
        sh[c] = h[c];
        sl[c] = l[c];
    }
}

// load fp32 A rows -> bf16 hi/lo swizzled SMEM (zero-fill rows >= M)
__device__ __forceinline__ void load_a(const float* X, int row0, int M,
                                       char* shp, char* slp, int tid) {
    uint4* sh = (uint4*)shp;
    uint4* sl = (uint4*)slp;
#pragma unroll
    for (int q = 0; q < 8; q++) {
        int c = tid + 256 * q;
        int r = c >> 4, ch = c & 15;
        int grow = row0 + r;
        float v[8];
#pragma unroll
        for (int j = 0; j < 8; j++) v[j] = 0.0f;
        if (grow < M) {
            const float4* p = (const float4*)(X + (size_t)grow * CH + ch * 8);
            float4 v0 = p[0], v1 = p[1];
            v[0] = v0.x; v[1] = v0.y; v[2] = v0.z; v[3] = v0.w;
            v[4] = v1.x; v[5] = v1.y; v[6] = v1.z; v[7] = v1.w;
        }
        unsigned hi[4], lo[4];
#pragma unroll
        for (int j = 0; j < 4; j++) {
            hi[j] = packbf(v[2 * j], v[2 * j + 1]);
            lo[j] = packbf(v[2 * j] - bflo(hi[j]), v[2 * j + 1] - bfhi(hi[j]));
        }
        int d = swz(r, ch);
        sh[d] = make_uint4(hi[0], hi[1], hi[2], hi[3]);
        sl[d] = make_uint4(lo[0], lo[1], lo[2], lo[3]);
    }
}

// ---------------- convW: bf16 hi/lo split of 10 weight matrices --------------
__global__ void convW(const float* __restrict__ W_init, const float* __restrict__ mlp_W,
                      unsigned* __restrict__ Whi, unsigned* __restrict__ Wlo) {
    const int m = blockIdx.x >> 3;
    const int seg = blockIdx.x & 7;
    const float* W = (m < 2) ? (W_init + (size_t)m * CH * CH)
                             : (mlp_W + (size_t)(m - 2) * CH * CH);
    const int t = seg * 1024 + threadIdx.x;
    for (int q = 0; q < 4; q++) {
        int tt = t + q * 256;
        float w0 = W[2 * tt], w1 = W[2 * tt + 1];
        unsigned hi = packbf(w0, w1);
        unsigned lo = packbf(w0 - bflo(hi), w1 - bfhi(hi));
        Whi[m * 8192 + tt] = hi;
        Wlo[m * 8192 + tt] = lo;
    }
}

// ---------------- CSR build ---------------------------------------------------
__global__ void hist2(const int* __restrict__ eui, const int* __restrict__ eiu,
                      int* __restrict__ cnt_i, int* __restrict__ cnt_u) {
    int e = blockIdx.x * blockDim.x + threadIdx.x;
    if (e >= NE) return;
    atomicAdd(&cnt_i[__ldg(&eui[NE + e])], 1);
    atomicAdd(&cnt_u[__ldg(&eiu[NE + e])], 1);
}

__global__ __launch_bounds__(1024) void scan2(int* __restrict__ cnt_i, int* __restrict__ rp_i,
                                              int* __restrict__ cnt_u, int* __restrict__ rp_u) {
    __shared__ int part[1024];
    const int n = blockIdx.x ? NU : NI;
    int* cnt = blockIdx.x ? cnt_u : cnt_i;
    int* rp = blockIdx.x ? rp_u : rp_i;
    const int tid = threadIdx.x;
    const int chunk = (n + 1023) / 1024;
    const int lo = tid * chunk;
    const int hi = (lo + chunk < n) ? lo + chunk : n;
    int s = 0;
    for (int i = lo; i < hi; i++) s += cnt[i];
    part[tid] = s;
    __syncthreads();
    for (int off = 1; off < 1024; off <<= 1) {
        int v = (tid >= off) ? part[tid - off] : 0;
        __syncthreads();
        part[tid] += v;
        __syncthreads();
    }
    int run = tid ? part[tid - 1] : 0;
    for (int i = lo; i < hi; i++) {
        int c = cnt[i];
        rp[i] = run;
        cnt[i] = run;
        run += c;
    }
    if (tid == 1023) rp[n] = run;
}

__global__ void fill2(const int* __restrict__ eui, const int* __restrict__ eiu,
                      int* __restrict__ cur_i, int* __restrict__ cur_u,
                      int* __restrict__ col_i, int* __restrict__ col_u) {
    int e = blockIdx.x * blockDim.x + threadIdx.x;
    if (e >= NE) return;
    int di = __ldg(&eui[NE + e]);
    col_i[atomicAdd(&cur_i[di], 1)] = __ldg(&eui[e]);
    int du = __ldg(&eiu[NE + e]);
    col_u[atomicAdd(&cur_u[du], 1)] = __ldg(&eiu[e]);
}

// ------ merged pull: (1+eps)*self + neighbor sum -> bf16 hi/lo tile images ---
__global__ void pull_all(const int* __restrict__ rp_i, const int* __restrict__ col_i,
                         const int* __restrict__ rp_u, const int* __restrict__ col_u,
                         const float* __restrict__ xu, const float* __restrict__ xi,
                         const float* __restrict__ eps2,
                         unsigned* __restrict__ ahi_i, unsigned* __restrict__ alo_i,
                         unsigned* __restrict__ ahi_u, unsigned* __restrict__ alo_u) {
    int w = (int)((blockIdx.x * (unsigned)blockDim.x + threadIdx.x) >> 5);
    int lane = threadIdx.x & 31;
    const int* rp;
    const int* col;
    const float* XG;
    const float* XS;
    unsigned* Ohi;
    unsigned* Olo;
    float alpha;
    int idx;
    if (w < NI) {
        idx = w; rp = rp_i; col = col_i; XG = xu; XS = xi;
        Ohi = ahi_i; Olo = alo_i;
        alpha = 1.0f + __ldg(&eps2[0]);
    } else {
        idx = w - NI;
        if (idx >= NU) return;
        rp = rp_u; col = col_u; XG = xi; XS = xu;
        Ohi = ahi_u; Olo = alo_u;
        alpha = 1.0f + __ldg(&eps2[1]);
    }
    const float4 sv = *(const float4*)(XS + (size_t)idx * CH + lane * 4);
    float ax = alpha * sv.x, ay = alpha * sv.y, az = alpha * sv.z, aw = alpha * sv.w;
    const int beg = __ldg(&rp[idx]);
    const int end = __ldg(&rp[idx + 1]);
    // masked quads: always 4 loads in flight (invalid -> duplicate row, masked)
    for (int j = beg; j < end; j += 4) {
        const int s0 = __ldg(&col[j]);
        const int s1 = (j + 1 < end) ? __ldg(&col[j + 1]) : s0;
        const int s2 = (j + 2 < end) ? __ldg(&col[j + 2]) : s0;
        const int s3 = (j + 3 < end) ? __ldg(&col[j + 3]) : s0;
        const float m1 = (j + 1 < end) ? 1.f : 0.f;
        const float m2 = (j + 2 < end) ? 1.f : 0.f;
        const float m3 = (j + 3 < end) ? 1.f : 0.f;
        const float4 v0 = *(const float4*)(XG + (size_t)s0 * CH + lane * 4);
        const float4 v1 = *(const float4*)(XG + (size_t)s1 * CH + lane * 4);
        const float4 v2 = *(const float4*)(XG + (size_t)s2 * CH + lane * 4);
        const float4 v3 = *(const float4*)(XG + (size_t)s3 * CH + lane * 4);
        ax += (v0.x + m1 * v1.x) + (m2 * v2.x + m3 * v3.x);
        ay += (v0.y + m1 * v1.y) + (m2 * v2.y + m3 * v3.y);
        az += (v0.z + m1 * v1.z) + (m2 * v2.z + m3 * v3.z);
        aw += (v0.w + m1 * v1.w) + (m2 * v2.w + m3 * v3.w);
    }
    // bf16 hi/lo split, write into swizzled tile image (mapping proven in R15)
    unsigned h0 = packbf(ax, ay), h1 = packbf(az, aw);
    unsigned l0 = packbf(ax - bflo(h0), ay - bfhi(h0));
    unsigned l1 = packbf(az - bflo(h1), aw - bfhi(h1));
    const int tile = idx >> 7, r = idx & 127;
    const size_t uoff = (size_t)tile * 8192 + swz(r, lane >> 1) * 4 + (lane & 1) * 2;
    *(uint2*)(Ohi + uoff) = make_uint2(h0, h1);
    *(uint2*)(Olo + uoff) = make_uint2(l0, l1);
}

// ---------------- merged init projection GEMM (user + item in one grid) ------
#define IG_WHI 0
#define IG_WLO 32768
#define IG_AHI 65536
#define IG_ALO 98304
#define IG_BIAS 131072
#define IG_TOT (131072 + 512)

__global__ __launch_bounds__(256) void init_gemm(
    const float* __restrict__ x_user, const float* __restrict__ x_item,
    const unsigned* __restrict__ Whi, const unsigned* __restrict__ Wlo,
    const float* __restrict__ b_init, float* __restrict__ xu, float* __restrict__ xi) {
    extern __shared__ char sm[];
    const int tid = threadIdx.x, wid = tid >> 5, lane = tid & 31;
    const bool user = blockIdx.x < TU;
    const int tile = user ? blockIdx.x : blockIdx.x - TU;
    const int M = user ? NU : NI;
    const int row0 = tile * 128;
    const float* X = user ? x_user : x_item;
    const int slot = user ? 0 : 1;
    const float* bias = b_init + (user ? 0 : CH);
    float* Y = user ? xu : xi;

    load_w32k(Whi + slot * 8192, sm + IG_WHI, tid);
    load_w32k(Wlo + slot * 8192, sm + IG_WLO, tid);
    load_a(X, row0, M, sm + IG_AHI, sm + IG_ALO, tid);
    if (tid < 128) ((float*)(sm + IG_BIAS))[tid] = bias[tid];
    __syncthreads();

    const int wm = wid & 1, wn = wid >> 1;
    const unsigned base = smem_u32(sm);
    float acc[4][4][4];
    do_gemm(base, IG_AHI, IG_ALO, IG_WHI, IG_WLO, wm, wn, lane, acc);

    const float* sbias = (const float*)(sm + IG_BIAS);
#pragma unroll
    for (int mi = 0; mi < 4; mi++) {
        const int r = row0 + wm * 64 + mi * 16 + (lane >> 2);
#pragma unroll
        for (int ni = 0; ni < 4; ni++) {
            const int cb = wn * 32 + ni * 8 + (lane & 3) * 2;
            const float b0 = sbias[cb], b1 = sbias[cb + 1];
            if (r < M)
                *(float2*)(Y + (size_t)r * CH + cb) =
                    make_float2(acc[mi][ni][0] + b0, acc[mi][ni][1] + b1);
            if (r + 8 < M)
                *(float2*)(Y + (size_t)(r + 8) * CH + cb) =
                    make_float2(acc[mi][ni][2] + b0, acc[mi][ni][3] + b1);
        }
    }
}

// ---------------- fused MLP (2 linears) + LayerNorm + ReLU -------------------
// blocks [0,TU) = user tiles, [TU,TU+TI) = item tiles; A comes as bf16 images
#define FM_W0HI 0
#define FM_W0LO 32768
#define FM_W1HI 65536
#define FM_W1LO 98304
#define FM_AHI  131072
#define FM_ALO  163840
#define FM_PAR  196608        // bias0,bias1,lng,lnb : 4 x 512B
#define FM_TOT  (196608 + 2048)

__global__ __launch_bounds__(256) void fused_mlp(
    const unsigned* __restrict__ ahi_u, const unsigned* __restrict__ alo_u,
    const unsigned* __restrict__ ahi_i, const unsigned* __restrict__ alo_i,
    const unsigned* __restrict__ Whi, const unsigned* __restrict__ Wlo,
    int slot_u0, int slot_i0,
    const float* __restrict__ Bu0, const float* __restrict__ Bu1,
    const float* __restrict__ Bi0, const float* __restrict__ Bi1,
    const float* __restrict__ lngu, const float* __restrict__ lnbu,
    const float* __restrict__ lngi, const float* __restrict__ lnbi,
    float* __restrict__ out_u, float* __restrict__ out_i) {
    extern __shared__ char sm[];
    const int tid = threadIdx.x, wid = tid >> 5, lane = tid & 31;
    const bool user = blockIdx.x < TU;
    const int tile = user ? blockIdx.x : blockIdx.x - TU;
    const int M = user ? NU : NI;
    const int row0 = tile * 128;
    const int s0 = user ? slot_u0 : slot_i0;
    const float* B0 = user ? Bu0 : Bi0;
    const float* B1 = user ? Bu1 : Bi1;
    const float* lg = user ? lngu : lngi;
    const float* lb = user ? lnbu : lnbi;
    float* Y = user ? out_u : out_i;
    const unsigned* Ah = (user ? ahi_u : ahi_i) + (size_t)tile * 8192;
    const unsigned* Al = (user ? alo_u : alo_i) + (size_t)tile * 8192;

    copy_a(Ah, Al, sm + FM_AHI, sm + FM_ALO, tid);
    load_w32k(Whi + (size_t)s0 * 8192, sm + FM_W0HI, tid);
    load_w32k(Wlo + (size_t)s0 * 8192, sm + FM_W0LO, tid);
    load_w32k(Whi + (size_t)(s0 + 1) * 8192, sm + FM_W1HI, tid);
    load_w32k(Wlo + (size_t)(s0 + 1) * 8192, sm + FM_W1LO, tid);
    if (tid < 128) {
        float* par = (float*)(sm + FM_PAR);
        par[tid] = B0[tid];
        par[128 + tid] = B1[tid];
        par[256 + tid] = lg[tid];
        par[384 + tid] = lb[tid];
    }
    __syncthreads();

    const int wm = wid & 1, wn = wid >> 1;
    const unsigned base = smem_u32(sm);
    const float* par = (const float*)(sm + FM_PAR);
    float acc[4][4][4];

    // ---- GEMM1 + bias0 + relu -> rewrite A tile (bf16 hi/lo) in SMEM ----
    do_gemm(base, FM_AHI, FM_ALO, FM_W0HI, FM_W0LO, wm, wn, lane, acc);
    __syncthreads();
#pragma unroll
    for (int mi = 0; mi < 4; mi++) {
        const int r0 = wm * 64 + mi * 16 + (lane >> 2);
#pragma unroll
        for (int ni = 0; ni < 4; ni++) {
            const int cb = wn * 32 + ni * 8 + (lane & 3) * 2;
            const float b0 = par[cb], b1 = par[cb + 1];
            float v0 = fmaxf(acc[mi][ni][0] + b0, 0.f);
            float v1 = fmaxf(acc[mi][ni][1] + b1, 0.f);
            float v2 = fmaxf(acc[mi][ni][2] + b0, 0.f);
            float v3 = fmaxf(acc[mi][ni][3] + b1, 0.f);
            const int boff0 = swz(r0, cb >> 3) * 16 + ((cb & 7) >> 1) * 4;
            const int boff1 = swz(r0 + 8, cb >> 3) * 16 + ((cb & 7) >> 1) * 4;
            unsigned hi = packbf(v0, v1);
            unsigned lo = packbf(v0 - bflo(hi), v1 - bfhi(hi));
            *(unsigned*)(sm + FM_AHI + boff0) = hi;
            *(unsigned*)(sm + FM_ALO + boff0) = lo;
            hi = packbf(v2, v3);
            lo = packbf(v2 - bflo(hi), v3 - bfhi(hi));
            *(unsigned*)(sm + FM_AHI + boff1) = hi;
            *(unsigned*)(sm + FM_ALO + boff1) = lo;
        }
    }
    __syncthreads();

    // ---- GEMM2 + bias1 + relu -> fp32 tile in SMEM (reuse A region) ----
    do_gemm(base, FM_AHI, FM_ALO, FM_W1HI, FM_W1LO, wm, wn, lane, acc);
    __syncthreads();
    float* ftile = (float*)(sm + FM_AHI);
#pragma unroll
    for (int mi = 0; mi < 4; mi++) {
        const int r0 = wm * 64 + mi * 16 + (lane >> 2);
#pragma unroll
        for (int ni = 0; ni < 4; ni++) {
            const int cb = wn * 32 + ni * 8 + (lane & 3) * 2;
            const float b0 = par[128 + cb], b1 = par[128 + cb + 1];
            *(float2*)&ftile[r0 * 128 + cb] =
                make_float2(fmaxf(acc[mi][ni][0] + b0, 0.f), fmaxf(acc[mi][ni][1] + b1, 0.f));
            *(float2*)&ftile[(r0 + 8) * 128 + cb] =
                make_float2(fmaxf(acc[mi][ni][2] + b0, 0.f), fmaxf(acc[mi][ni][3] + b1, 0.f));
        }
    }
    __syncthreads();

    // ---- LayerNorm + ReLU, warp per row, straight to global ----
    const float4 gv = *(const float4*)&par[256 + lane * 4];
    const float4 bv = *(const float4*)&par[384 + lane * 4];
#pragma unroll
    for (int k = 0; k < 16; k++) {
        const int r = wid * 16 + k;
        const int grow = row0 + r;
        if (grow >= M) break;
        const float4 v = *(const float4*)&ftile[r * 128 + lane * 4];
        float s = v.x + v.y + v.z + v.w;
#pragma unroll
        for (int o = 16; o > 0; o >>= 1) s += __shfl_xor_sync(0xffffffffu, s, o);
        float m = s * (1.0f / CH);
        float dx0 = v.x - m, dx1 = v.y - m, dx2 = v.z - m, dx3 = v.w - m;
        float ss = dx0 * dx0 + dx1 * dx1 + dx2 * dx2 + dx3 * dx3;
#pragma unroll
        for (int o = 16; o > 0; o >>= 1) ss += __shfl_xor_sync(0xffffffffu, ss, o);
        float inv = rsqrtf(ss * (1.0f / CH) + 1e-5f);
        float4 o4;
        o4.x = fmaxf(dx0 * inv * gv.x + bv.x, 0.0f);
        o4.y = fmaxf(dx1 * inv * gv.y + bv.y, 0.0f);
        o4.z = fmaxf(dx2 * inv * gv.z + bv.z, 0.0f);
        o4.w = fmaxf(dx3 * inv * gv.w + bv.w, 0.0f);
        *(float4*)(Y + (size_t)grow * CH + lane * 4) = o4;
    }
}

// ---------------- orchestration ---------------------------------------------
extern "C" void kernel_launch(void* const* d_in, const int* in_sizes, int n_in,
                              void* d_out, int out_size) {
    const float* x_user = (const float*)d_in[0];
    const float* x_item = (const float*)d_in[1];
    const float* W_init = (const float*)d_in[2];
    const float* b_init = (const float*)d_in[3];
    const float* mlp_W  = (const float*)d_in[4];
    const float* mlp_b  = (const float*)d_in[5];
    const float* eps    = (const float*)d_in[6];
    const float* ln_g   = (const float*)d_in[7];
    const float* ln_b   = (const float*)d_in[8];
    const int* edge_ui  = (const int*)d_in[9];
    const int* edge_iu  = (const int*)d_in[10];

    float *xu, *xi;
    unsigned *Wh, *Wl, *ahu, *alu, *ahi, *ali;
    int *rp_u, *rp_i, *cnt_u, *cnt_i, *col_u, *col_i;
    cudaGetSymbolAddress((void**)&xu, g_xu);
    cudaGetSymbolAddress((void**)&xi, g_xi);
    cudaGetSymbolAddress((void**)&ahu, g_agh_u);
    cudaGetSymbolAddress((void**)&alu, g_agl_u);
    cudaGetSymbolAddress((void**)&ahi, g_agh_i);
    cudaGetSymbolAddress((void**)&ali, g_agl_i);
    cudaGetSymbolAddress((void**)&Wh, g_W_hi);
    cudaGetSymbolAddress((void**)&Wl, g_W_lo);
    cudaGetSymbolAddress((void**)&rp_u, g_rp_u);
    cudaGetSymbolAddress((void**)&rp_i, g_rp_i);
    cudaGetSymbolAddress((void**)&cnt_u, g_cnt_u);
    cudaGetSymbolAddress((void**)&cnt_i, g_cnt_i);
    cudaGetSymbolAddress((void**)&col_u, g_col_u);
    cudaGetSymbolAddress((void**)&col_i, g_col_i);

    cudaFuncSetAttribute(init_gemm, cudaFuncAttributeMaxDynamicSharedMemorySize, IG_TOT);
    cudaFuncSetAttribute(fused_mlp, cudaFuncAttributeMaxDynamicSharedMemorySize, FM_TOT);

    const int eblk = (NE + 255) / 256;
    const int pall = ((NI + NU) * 32 + 255) / 256;

    // ---- CSR build (both directions) ----
    cudaMemsetAsync(cnt_u, 0, NU * sizeof(int), 0);
    cudaMemsetAsync(cnt_i, 0, NI * sizeof(int), 0);
    hist2<<<eblk, 256>>>(edge_ui, edge_iu, cnt_i, cnt_u);
    scan2<<<2, 1024>>>(cnt_i, rp_i, cnt_u, rp_u);
    fill2<<<eblk, 256>>>(edge_ui, edge_iu, cnt_i, cnt_u, col_i, col_u);

    // ---- weights: bf16 hi/lo split once ----
    convW<<<80, 256>>>(W_init, mlp_W, Wh, Wl);

    // ---- init projections (merged user+item) ----
    init_gemm<<<TU + TI, 256, IG_TOT>>>(x_user, x_item, Wh, Wl, b_init, xu, xi);

    for (int l = 0; l < NLAY; l++) {
        pull_all<<<pall, 256>>>(rp_i, col_i, rp_u, col_u, xu, xi, eps + l * 2,
                                ahi, ali, ahu, alu);

        const int si0 = 2 + (l * 2 + 0) * 2;   // item MLP slots (edge type 0)
        const int su0 = 2 + (l * 2 + 1) * 2;   // user MLP slots (edge type 1)
        const float* Bi0 = mlp_b + (size_t)((l * 2 + 0) * 2 + 0) * CH;
        const float* Bi1 = mlp_b + (size_t)((l * 2 + 0) * 2 + 1) * CH;
        const float* Bu0 = mlp_b + (size_t)((l * 2 + 1) * 2 + 0) * CH;
        const float* Bu1 = mlp_b + (size_t)((l * 2 + 1) * 2 + 1) * CH;

        float* ou = (l == NLAY - 1) ? (float*)d_out : xu;
        float* oi = (l == NLAY - 1) ? (float*)d_out + (size_t)NU * CH : xi;
        fused_mlp<<<TU + TI, 256, FM_TOT>>>(
            ahu, alu, ahi, ali, Wh, Wl, su0, si0, Bu0, Bu1, Bi0, Bi1,
            ln_g + (l * 2 + 0) * CH, ln_b + (l * 2 + 0) * CH,
            ln_g + (l * 2 + 1) * CH, ln_b + (l * 2 + 1) * CH,
            ou, oi);
    }
}